// round 15
// baseline (speedup 1.0000x reference)
#include <cuda_runtime.h>
#include <math.h>

#define B 512
#define SEQ 128
#define CIN 32
#define HID 64
#define NH 8
#define D1 (NH * HID)
#define NEG_SLOPE 0.2f
#define NEG_INF -1000000000.0f

typedef unsigned long long ull;
__device__ __forceinline__ void ffma2(ull& d, ull a, ull b) {
    asm("fma.rn.f32x2 %0, %1, %2, %0;" : "+l"(d) : "l"(a), "l"(b));
}
__device__ __forceinline__ ull splat2(float v) {
    ull r; asm("mov.b64 %0, {%1, %1};" : "=l"(r) : "f"(v)); return r;
}
__device__ __forceinline__ float2 unpack2(ull v) {
    float2 f; asm("mov.b64 {%0, %1}, %2;" : "=f"(f.x), "=f"(f.y) : "l"(v)); return f;
}
__device__ __forceinline__ void bulkcp(unsigned dst, const void* src, unsigned bytes,
                                       unsigned mbar) {
    asm volatile("cp.async.bulk.shared::cta.global.mbarrier::complete_tx::bytes "
                 "[%0], [%1], %2, [%3];"
                 :: "r"(dst), "l"(src), "r"(bytes), "r"(mbar) : "memory");
}
__device__ __forceinline__ void mbar_init(unsigned mbar, unsigned cnt) {
    asm volatile("mbarrier.init.shared.b64 [%0], %1;" :: "r"(mbar), "r"(cnt) : "memory");
}
__device__ __forceinline__ void mbar_expect(unsigned mbar, unsigned bytes) {
    asm volatile("mbarrier.arrive.expect_tx.shared.b64 _, [%0], %1;"
                 :: "r"(mbar), "r"(bytes) : "memory");
}
__device__ __forceinline__ void mbar_wait(unsigned mbar, unsigned parity) {
    asm volatile(
        "{\n\t.reg .pred P;\n\t"
        "W%=:\n\t"
        "mbarrier.try_wait.parity.acquire.cta.shared::cta.b64 P, [%0], %1, 0x989680;\n\t"
        "@P bra D%=;\n\t"
        "bra W%=;\n\t"
        "D%=:\n\t}"
        :: "r"(mbar), "r"(parity) : "memory");
}

__device__ float    g_h1[B * SEQ * D1];
__device__ float    g_out1[B * SEQ * D1];
__device__ float    g_h2[B * SEQ * HID];
__device__ unsigned g_mask[B * SEQ * 4];

// ============ K0: pack mask bits: mask[b,t,s] = adj[b,1,s,t]!=0 || s==t ============
__global__ void k0_maskpack(const int* __restrict__ adj) {
    int b = blockIdx.x, t = threadIdx.x;
    const int* A = adj + ((size_t)b * 2 + 1) * SEQ * SEQ;
#pragma unroll
    for (int w = 0; w < 4; w++) {
        unsigned bits = 0u;
#pragma unroll
        for (int j = 0; j < 32; j++)
            if (A[(w * 32 + j) * SEQ + t] != 0) bits |= (1u << j);
        if ((t >> 5) == w) bits |= (1u << (t & 31));
        g_mask[((size_t)b * SEQ + t) * 4 + w] = bits;
    }
}

// ============ K1: h1 = x @ W1 (M=65536,K=32,N=512), FFMA2 row-pair packed ============
__global__ __launch_bounds__(256) void k1_gemm1(const float* __restrict__ x,
                                                const float* __restrict__ W1) {
    __shared__ float xs_t[CIN * 16];
    int tid = threadIdx.x, row0 = blockIdx.x * 16;
    if (tid < 128) {
        int r = tid >> 3, q = tid & 7;
        float4 v = *(const float4*)(x + (size_t)(row0 + r) * CIN + q * 4);
        xs_t[(4 * q + 0) * 16 + r] = v.x; xs_t[(4 * q + 1) * 16 + r] = v.y;
        xs_t[(4 * q + 2) * 16 + r] = v.z; xs_t[(4 * q + 3) * 16 + r] = v.w;
    }
    __syncthreads();
    int cg = (tid & 127) * 4, rb = (tid >> 7) * 8;
    ull acc2[4][4];
#pragma unroll
    for (int p = 0; p < 4; p++) { acc2[p][0]=0; acc2[p][1]=0; acc2[p][2]=0; acc2[p][3]=0; }
#pragma unroll
    for (int k = 0; k < CIN; k++) {
        float4 w = *(const float4*)(W1 + (size_t)k * D1 + cg);
        ull w0 = splat2(w.x), w1 = splat2(w.y), w2 = splat2(w.z), w3 = splat2(w.w);
        ulonglong2 xa = *(const ulonglong2*)&xs_t[k * 16 + rb];
        ulonglong2 xb = *(const ulonglong2*)&xs_t[k * 16 + rb + 4];
        ffma2(acc2[0][0], xa.x, w0); ffma2(acc2[0][1], xa.x, w1);
        ffma2(acc2[0][2], xa.x, w2); ffma2(acc2[0][3], xa.x, w3);
        ffma2(acc2[1][0], xa.y, w0); ffma2(acc2[1][1], xa.y, w1);
        ffma2(acc2[1][2], xa.y, w2); ffma2(acc2[1][3], xa.y, w3);
        ffma2(acc2[2][0], xb.x, w0); ffma2(acc2[2][1], xb.x, w1);
        ffma2(acc2[2][2], xb.x, w2); ffma2(acc2[2][3], xb.x, w3);
        ffma2(acc2[3][0], xb.y, w0); ffma2(acc2[3][1], xb.y, w1);
        ffma2(acc2[3][2], xb.y, w2); ffma2(acc2[3][3], xb.y, w3);
    }
#pragma unroll
    for (int p = 0; p < 4; p++) {
        float2 v0 = unpack2(acc2[p][0]), v1 = unpack2(acc2[p][1]);
        float2 v2 = unpack2(acc2[p][2]), v3 = unpack2(acc2[p][3]);
        int r = row0 + rb + 2 * p;
        *(float4*)(g_h1 + (size_t)r * D1 + cg)       = make_float4(v0.x, v1.x, v2.x, v3.x);
        *(float4*)(g_h1 + (size_t)(r + 1) * D1 + cg) = make_float4(v0.y, v1.y, v2.y, v3.y);
    }
}

// ============ K2: fused GAT1 attention, 8t x 8c c-pair FFMA2 (round-14, at FMA floor) ==
#define HST 68
#define AWT2 132
#define K2_SMEM ((SEQ*HST + SEQ*AWT2 + SEQ + SEQ + HID + HID + SEQ) * 4 + SEQ * 4 * 4)

__global__ __launch_bounds__(128) void k2_gat1(const float* __restrict__ a_src,
                                               const float* __restrict__ a_dst,
                                               const float* __restrict__ b1) {
    extern __shared__ float sm[];
    float*    hs   = sm;
    float*    aw   = hs + SEQ * HST;
    float*    esrc = aw + SEQ * AWT2;
    float*    edst = esrc + SEQ;
    float*    avs  = edst + SEQ;
    float*    avd  = avs + HID;
    float*    rdsm = avd + HID;
    unsigned* mw   = (unsigned*)(rdsm + SEQ);

    int b = blockIdx.x, h = blockIdx.y;
    int tid = threadIdx.x, wid = tid >> 5, ln = tid & 31;

    const float* hb = g_h1 + ((size_t)b * SEQ) * D1 + h * HID;
    for (int i = tid; i < 2048; i += 128) {
        int s = i >> 4, q = i & 15;
        *(float4*)&hs[s * HST + 4 * q] = *(const float4*)(hb + (size_t)s * D1 + 4 * q);
    }
    if (tid < HID) { avs[tid] = a_src[h * HID + tid]; avd[tid] = a_dst[h * HID + tid]; }
    for (int i = tid; i < SEQ * 4; i += 128) mw[i] = g_mask[(size_t)b * SEQ * 4 + i];
    __syncthreads();

    {
        const float* hr = hs + tid * HST;
        float ps = 0.f, pd = 0.f;
#pragma unroll
        for (int c4 = 0; c4 < 16; c4++) {
            float4 hv = *(const float4*)&hr[4 * c4];
            float4 as = *(const float4*)&avs[4 * c4];
            float4 ad = *(const float4*)&avd[4 * c4];
            ps += hv.x * as.x + hv.y * as.y + hv.z * as.z + hv.w * as.w;
            pd += hv.x * ad.x + hv.y * ad.y + hv.z * ad.z + hv.w * ad.w;
        }
        esrc[tid] = ps; edst[tid] = pd;
    }
    __syncthreads();

    int tp = ln >> 3, cl = ln & 7;
    int cb = cl * 4;
    int s0 = ln * 4, sh = cl * 4;
    float4 es4 = *(const float4*)&esrc[s0];
    float* awme = aw + wid * 32 * AWT2;
    float4 ba = *(const float4*)(b1 + h * HID + cb);
    float4 bbq = *(const float4*)(b1 + h * HID + cb + 32);

    for (int tl = 0; tl < 32; tl++) {
        int t = wid * 32 + tl;
        float ed = edst[t];
        unsigned mword = mw[t * 4 + tp];
        float l0 = es4.x + ed; l0 = l0 > 0.f ? l0 : NEG_SLOPE * l0;
        float l1 = es4.y + ed; l1 = l1 > 0.f ? l1 : NEG_SLOPE * l1;
        float l2 = es4.z + ed; l2 = l2 > 0.f ? l2 : NEG_SLOPE * l2;
        float l3 = es4.w + ed; l3 = l3 > 0.f ? l3 : NEG_SLOPE * l3;
        if (!((mword >> (sh + 0)) & 1u)) l0 = NEG_INF;
        if (!((mword >> (sh + 1)) & 1u)) l1 = NEG_INF;
        if (!((mword >> (sh + 2)) & 1u)) l2 = NEG_INF;
        if (!((mword >> (sh + 3)) & 1u)) l3 = NEG_INF;
        *(float4*)&awme[tl * AWT2 + s0] =
            make_float4(__expf(l0), __expf(l1), __expf(l2), __expf(l3));
    }
    __syncwarp();

    {
        const float* row = &awme[ln * AWT2];
        ull s2 = 0ull, one = splat2(1.0f);
#pragma unroll 8
        for (int qq = 0; qq < 32; qq++) {
            ulonglong2 v = *(const ulonglong2*)&row[4 * qq];
            ffma2(s2, v.x, one); ffma2(s2, v.y, one);
        }
        float2 f = unpack2(s2);
        rdsm[wid * 32 + ln] = 1.0f / (f.x + f.y);
    }
    __syncwarp();

    ull acc2[8][4];
#pragma unroll
    for (int i = 0; i < 8; i++) { acc2[i][0]=0; acc2[i][1]=0; acc2[i][2]=0; acc2[i][3]=0; }

#pragma unroll 4
    for (int s = 0; s < SEQ; s++) {
        const float* hrow = hs + s * HST;
        ulonglong2 hA = *(const ulonglong2*)&hrow[cb];
        ulonglong2 hB = *(const ulonglong2*)&hrow[cb + 32];
#pragma unroll
        for (int i = 0; i < 8; i++) {
            float wv = awme[(tp + 4 * i) * AWT2 + s];
            ull ws = splat2(wv);
            ffma2(acc2[i][0], ws, hA.x); ffma2(acc2[i][1], ws, hA.y);
            ffma2(acc2[i][2], ws, hB.x); ffma2(acc2[i][3], ws, hB.y);
        }
    }

#pragma unroll
    for (int i = 0; i < 8; i++) {
        int t = wid * 32 + tp + 4 * i;
        float rd = rdsm[t];
        float* dst = g_out1 + ((size_t)b * SEQ + t) * D1 + h * HID;
        float2 a = unpack2(acc2[i][0]), bq = unpack2(acc2[i][1]);
        float2 c = unpack2(acc2[i][2]), d = unpack2(acc2[i][3]);
        *(float4*)(dst + cb) = make_float4(
            fmaxf(a.x * rd + ba.x, 0.f), fmaxf(a.y * rd + ba.y, 0.f),
            fmaxf(bq.x * rd + ba.z, 0.f), fmaxf(bq.y * rd + ba.w, 0.f));
        *(float4*)(dst + cb + 32) = make_float4(
            fmaxf(c.x * rd + bbq.x, 0.f), fmaxf(c.y * rd + bbq.y, 0.f),
            fmaxf(d.x * rd + bbq.z, 0.f), fmaxf(d.y * rd + bbq.w, 0.f));
    }
}

// ============ K3: h2 = out1 @ W2, 4r x 8c lanes, cp.async.bulk + mbarrier DB ============
// K3R=128 rows/block, 256 thr, 3 blocks/SM (grid 512 -> 1.15 waves).
// Staging via cp.async.bulk row copies (1 instr / 128B x-row, / 256B W2-row) issued by
// tid 0, transaction-counted on per-buffer mbarrier -> kills the per-16B cp.async
// issue tax (10.5M ops -> 1.3M). Buffer bf serves chunks c (c&1==bf); parity (c>>1)&1.
#define KC 32
#define XST 36
#define K3R 128
#define K3_XSF (K3R * XST)
#define K3_WSF (KC * 64)
#define K3_MBAR_OFF ((2 * K3_XSF + 2 * K3_WSF) * 4)
#define K3_SMEM (K3_MBAR_OFF + 16)
#define K3_BYTES (K3R * 128 + KC * 256)

__global__ __launch_bounds__(256, 3) void k3_gemm2(const float* __restrict__ W2) {
    extern __shared__ float k3sm[];
    int tid = threadIdx.x, wid = tid >> 5, ln = tid & 31;
    int row0 = blockIdx.x * K3R;
    int rb = wid * 16 + (ln >> 3) * 4;     // 4 consecutive rows
    int cb = (ln & 7) * 4;

    unsigned smbase;
    { unsigned long long gp = __cvta_generic_to_shared(k3sm); smbase = (unsigned)gp; }
    unsigned mbar0 = smbase + K3_MBAR_OFF, mbar1 = mbar0 + 8;

    if (tid == 0) { mbar_init(mbar0, 1); mbar_init(mbar1, 1); }
    __syncthreads();

    auto stage = [&](int bf, int k0) {
        if (tid == 0) {
            unsigned mb = bf ? mbar1 : mbar0;
            mbar_expect(mb, K3_BYTES);
            unsigned xsb = smbase + (unsigned)(bf * K3_XSF) * 4u;
            unsigned wsb = smbase + (unsigned)(2 * K3_XSF + bf * K3_WSF) * 4u;
            const float* xsrc = g_out1 + (size_t)row0 * D1 + k0;
#pragma unroll 4
            for (int r = 0; r < K3R; r++)
                bulkcp(xsb + (unsigned)(r * XST) * 4u, xsrc + (size_t)r * D1, 128, mb);
            const float* wsrc = W2 + (size_t)k0 * HID;
#pragma unroll 4
            for (int kk = 0; kk < KC; kk++)
                bulkcp(wsb + (unsigned)(kk * 64) * 4u, wsrc + (size_t)kk * HID, 256, mb);
        }
    };

    ull acc2[4][4];
#pragma unroll
    for (int p = 0; p < 4; p++) { acc2[p][0]=0; acc2[p][1]=0; acc2[p][2]=0; acc2[p][3]=0; }

    stage(0, 0);

    for (int c = 0; c < D1 / KC; c++) {
        if (c < D1 / KC - 1) stage((c + 1) & 1, (c + 1) * KC);
        mbar_wait((c & 1) ? mbar1 : mbar0, (c >> 1) & 1);
        __syncthreads();

        const float* xs = k3sm + (c & 1) * K3_XSF;
        const float* ws = k3sm + 2 * K3_XSF + (c & 1) * K3_WSF;
#pragma unroll
        for (int k = 0; k < KC; k++) {
            ulonglong2 wA = *(const ulonglong2*)&ws[k * 64 + cb];
            ulonglong2 wB = *(const ulonglong2*)&ws[k * 64 + cb + 32];
            float x0 = xs[(rb + 0) * XST + k];
            float x1 = xs[(rb + 1) * XST + k];
            float x2 = xs[(rb + 2) * XST + k];
            float x3 = xs[(rb + 3) * XST + k];
            ull s0 = splat2(x0), s1 = splat2(x1), s2 = splat2(x2), s3 = splat2(x3);
            ffma2(acc2[0][0], s0, wA.x); ffma2(acc2[0][1], s0, wA.y);
            ffma2(acc2[0][2], s0, wB.x); ffma2(acc2[0][3], s0, wB.y);
            ffma2(acc2[1][0], s1, wA.x); ffma2(acc2[1][1], s1, wA.y);
            ffma2(acc2[1][2], s1, wB.x); ffma2(acc2[1][3], s1, wB.y);
            ffma2(acc2[2][0], s2, wA.x); ffma2(acc2[2][1], s2, wA.y);
            ffma2(acc2[2][2], s2, wB.x); ffma2(acc2[2][3], s2, wB.y);
            ffma2(acc2[3][0], s3, wA.x); ffma2(acc2[3][1], s3, wA.y);
            ffma2(acc2[3][2], s3, wB.x); ffma2(acc2[3][3], s3, wB.y);
        }
        __syncthreads();
    }
#pragma unroll
    for (int p = 0; p < 4; p++) {
        int r = row0 + rb + p;
        float2 a = unpack2(acc2[p][0]), bq = unpack2(acc2[p][1]);
        float2 c2 = unpack2(acc2[p][2]), d = unpack2(acc2[p][3]);
        *(float4*)(g_h2 + (size_t)r * HID + cb)      = make_float4(a.x, a.y, bq.x, bq.y);
        *(float4*)(g_h2 + (size_t)r * HID + cb + 32) = make_float4(c2.x, c2.y, d.x, d.y);
    }
}

// ============ K4: layer-2 attention at t=S-1 only + final head ============
__global__ __launch_bounds__(128) void k4_final(const float* __restrict__ a_src2,
                                                const float* __restrict__ a_dst2,
                                                const float* __restrict__ b2,
                                                const float* __restrict__ Wf,
                                                const float* __restrict__ bf,
                                                float* __restrict__ out) {
    __shared__ float hsm[SEQ * HID];
    __shared__ float e2[SEQ];
    __shared__ float wsm[SEQ];
    __shared__ float sred[2];
    __shared__ float sinv, sed;
    int b = blockIdx.x;
    int tid = threadIdx.x, wid = tid >> 5, ln = tid & 31;

    for (int i = tid; i < SEQ * HID / 4; i += 128)
        *(float4*)&hsm[i * 4] = *(const float4*)(g_h2 + (size_t)b * SEQ * HID + i * 4);
    __syncthreads();

    for (int i = 0; i < 32; i++) {
        int s = wid * 32 + i;
        float ps = hsm[s * HID + ln] * a_src2[ln] + hsm[s * HID + ln + 32] * a_src2[ln + 32];
#pragma unroll
        for (int o = 16; o; o >>= 1) ps += __shfl_down_sync(~0u, ps, o);
        if (ln == 0) e2[s] = ps;
    }
    if (wid == 0) {
        float pd = hsm[127 * HID + ln] * a_dst2[ln] + hsm[127 * HID + ln + 32] * a_dst2[ln + 32];
#pragma unroll
        for (int o = 16; o; o >>= 1) pd += __shfl_down_sync(~0u, pd, o);
        if (ln == 0) sed = pd;
    }
    __syncthreads();

    if (wid == 0) {
        float ed = sed;
        int s0 = ln * 4;
        unsigned mword = g_mask[((size_t)b * SEQ + 127) * 4 + (ln >> 3)];
        int sh = (ln & 7) * 4;
        float l0 = e2[s0 + 0] + ed; l0 = l0 > 0.f ? l0 : NEG_SLOPE * l0;
        float l1 = e2[s0 + 1] + ed; l1 = l1 > 0.f ? l1 : NEG_SLOPE * l1;
        float l2 = e2[s0 + 2] + ed; l2 = l2 > 0.f ? l2 : NEG_SLOPE * l2;
        float l3 = e2[s0 + 3] + ed; l3 = l3 > 0.f ? l3 : NEG_SLOPE * l3;
        if (!((mword >> (sh + 0)) & 1u)) l0 = NEG_INF;
        if (!((mword >> (sh + 1)) & 1u)) l1 = NEG_INF;
        if (!((mword >> (sh + 2)) & 1u)) l2 = NEG_INF;
        if (!((mword >> (sh + 3)) & 1u)) l3 = NEG_INF;
        float w0 = __expf(l0), w1 = __expf(l1);
        float w2 = __expf(l2), w3 = __expf(l3);
        float su = (w0 + w1) + (w2 + w3);
#pragma unroll
        for (int o = 16; o; o >>= 1) su += __shfl_xor_sync(~0u, su, o);
        *(float4*)&wsm[s0] = make_float4(w0, w1, w2, w3);
        if (ln == 0) sinv = 1.0f / su;
    }
    __syncthreads();

    float val = 0.f;
    if (tid < HID) {
        float acc = 0.f;
        for (int s = 0; s < SEQ; s++) acc = fmaf(wsm[s], hsm[s * HID + tid], acc);
        val = fmaxf(acc * sinv + b2[tid], 0.f) * Wf[tid];
    }
#pragma unroll
    for (int o = 16; o; o >>= 1) val += __shfl_down_sync(~0u, val, o);
    if (ln == 0 && wid < 2) sred[wid] = val;
    __syncthreads();
    if (tid == 0) out[b] = 1.0f / (1.0f + __expf(-(sred[0] + sred[1] + bf[0])));
}

// ============ launch ============
extern "C" void kernel_launch(void* const* d_in, const int* in_sizes, int n_in,
                              void* d_out, int out_size) {
    const float* x      = (const float*)d_in[0];
    const int*   adj    = (const int*)d_in[1];
    const float* W1     = (const float*)d_in[2];
    const float* a_src1 = (const float*)d_in[3];
    const float* a_dst1 = (const float*)d_in[4];
    const float* b1     = (const float*)d_in[5];
    const float* W2     = (const float*)d_in[6];
    const float* a_src2 = (const float*)d_in[7];
    const float* a_dst2 = (const float*)d_in[8];
    const float* b2     = (const float*)d_in[9];
    const float* Wf     = (const float*)d_in[10];
    const float* bf     = (const float*)d_in[11];
    float* out = (float*)d_out;

    cudaFuncSetAttribute(k2_gat1, cudaFuncAttributeMaxDynamicSharedMemorySize, K2_SMEM);
    cudaFuncSetAttribute(k3_gemm2, cudaFuncAttributeMaxDynamicSharedMemorySize, K3_SMEM);

    k0_maskpack<<<B, SEQ>>>(adj);
    k1_gemm1<<<(B * SEQ) / 16, 256>>>(x, W1);
    k2_gat1<<<dim3(B, NH), 128, K2_SMEM>>>(a_src1, a_dst1, b1);
    k3_gemm2<<<(B * SEQ) / K3R, 256, K3_SMEM>>>(W2);
    k4_final<<<B, 128>>>(a_src2, a_dst2, b2, Wf, bf, out);
}

// round 16
// speedup vs baseline: 1.0005x; 1.0005x over previous
#include <cuda_runtime.h>
#include <math.h>

#define B 512
#define SEQ 128
#define CIN 32
#define HID 64
#define NH 8
#define D1 (NH * HID)
#define NEG_SLOPE 0.2f
#define NEG_INF -1000000000.0f

typedef unsigned long long ull;
__device__ __forceinline__ void ffma2(ull& d, ull a, ull b) {
    asm("fma.rn.f32x2 %0, %1, %2, %0;" : "+l"(d) : "l"(a), "l"(b));
}
__device__ __forceinline__ ull splat2(float v) {
    ull r; asm("mov.b64 %0, {%1, %1};" : "=l"(r) : "f"(v)); return r;
}
__device__ __forceinline__ float2 unpack2(ull v) {
    float2 f; asm("mov.b64 {%0, %1}, %2;" : "=f"(f.x), "=f"(f.y) : "l"(v)); return f;
}
__device__ __forceinline__ void bulkcp(unsigned dst, const void* src, unsigned bytes,
                                       unsigned mbar) {
    asm volatile("cp.async.bulk.shared::cta.global.mbarrier::complete_tx::bytes "
                 "[%0], [%1], %2, [%3];"
                 :: "r"(dst), "l"(src), "r"(bytes), "r"(mbar) : "memory");
}
__device__ __forceinline__ void mbar_init(unsigned mbar, unsigned cnt) {
    asm volatile("mbarrier.init.shared.b64 [%0], %1;" :: "r"(mbar), "r"(cnt) : "memory");
}
__device__ __forceinline__ void mbar_expect(unsigned mbar, unsigned bytes) {
    asm volatile("mbarrier.arrive.expect_tx.shared.b64 _, [%0], %1;"
                 :: "r"(mbar), "r"(bytes) : "memory");
}
__device__ __forceinline__ void mbar_wait(unsigned mbar, unsigned parity) {
    asm volatile(
        "{\n\t.reg .pred P;\n\t"
        "W%=:\n\t"
        "mbarrier.try_wait.parity.acquire.cta.shared::cta.b64 P, [%0], %1, 0x989680;\n\t"
        "@P bra D%=;\n\t"
        "bra W%=;\n\t"
        "D%=:\n\t}"
        :: "r"(mbar), "r"(parity) : "memory");
}

__device__ float    g_h1[B * SEQ * D1];
__device__ float    g_out1[B * SEQ * D1];
__device__ float    g_h2[B * SEQ * HID];
__device__ unsigned g_mask[B * SEQ * 4];

// ============ K0: pack mask bits: mask[b,t,s] = adj[b,1,s,t]!=0 || s==t ============
__global__ void k0_maskpack(const int* __restrict__ adj) {
    int b = blockIdx.x, t = threadIdx.x;
    const int* A = adj + ((size_t)b * 2 + 1) * SEQ * SEQ;
#pragma unroll
    for (int w = 0; w < 4; w++) {
        unsigned bits = 0u;
#pragma unroll
        for (int j = 0; j < 32; j++)
            if (A[(w * 32 + j) * SEQ + t] != 0) bits |= (1u << j);
        if ((t >> 5) == w) bits |= (1u << (t & 31));
        g_mask[((size_t)b * SEQ + t) * 4 + w] = bits;
    }
}

// ============ K1: h1 = x @ W1 (M=65536,K=32,N=512), FFMA2 row-pair packed ============
__global__ __launch_bounds__(256) void k1_gemm1(const float* __restrict__ x,
                                                const float* __restrict__ W1) {
    __shared__ float xs_t[CIN * 16];
    int tid = threadIdx.x, row0 = blockIdx.x * 16;
    if (tid < 128) {
        int r = tid >> 3, q = tid & 7;
        float4 v = *(const float4*)(x + (size_t)(row0 + r) * CIN + q * 4);
        xs_t[(4 * q + 0) * 16 + r] = v.x; xs_t[(4 * q + 1) * 16 + r] = v.y;
        xs_t[(4 * q + 2) * 16 + r] = v.z; xs_t[(4 * q + 3) * 16 + r] = v.w;
    }
    __syncthreads();
    int cg = (tid & 127) * 4, rb = (tid >> 7) * 8;
    ull acc2[4][4];
#pragma unroll
    for (int p = 0; p < 4; p++) { acc2[p][0]=0; acc2[p][1]=0; acc2[p][2]=0; acc2[p][3]=0; }
#pragma unroll
    for (int k = 0; k < CIN; k++) {
        float4 w = *(const float4*)(W1 + (size_t)k * D1 + cg);
        ull w0 = splat2(w.x), w1 = splat2(w.y), w2 = splat2(w.z), w3 = splat2(w.w);
        ulonglong2 xa = *(const ulonglong2*)&xs_t[k * 16 + rb];
        ulonglong2 xb = *(const ulonglong2*)&xs_t[k * 16 + rb + 4];
        ffma2(acc2[0][0], xa.x, w0); ffma2(acc2[0][1], xa.x, w1);
        ffma2(acc2[0][2], xa.x, w2); ffma2(acc2[0][3], xa.x, w3);
        ffma2(acc2[1][0], xa.y, w0); ffma2(acc2[1][1], xa.y, w1);
        ffma2(acc2[1][2], xa.y, w2); ffma2(acc2[1][3], xa.y, w3);
        ffma2(acc2[2][0], xb.x, w0); ffma2(acc2[2][1], xb.x, w1);
        ffma2(acc2[2][2], xb.x, w2); ffma2(acc2[2][3], xb.x, w3);
        ffma2(acc2[3][0], xb.y, w0); ffma2(acc2[3][1], xb.y, w1);
        ffma2(acc2[3][2], xb.y, w2); ffma2(acc2[3][3], xb.y, w3);
    }
#pragma unroll
    for (int p = 0; p < 4; p++) {
        float2 v0 = unpack2(acc2[p][0]), v1 = unpack2(acc2[p][1]);
        float2 v2 = unpack2(acc2[p][2]), v3 = unpack2(acc2[p][3]);
        int r = row0 + rb + 2 * p;
        *(float4*)(g_h1 + (size_t)r * D1 + cg)       = make_float4(v0.x, v1.x, v2.x, v3.x);
        *(float4*)(g_h1 + (size_t)(r + 1) * D1 + cg) = make_float4(v0.y, v1.y, v2.y, v3.y);
    }
}

// ============ K2: fused GAT1 attention, 8t x 8c c-pair FFMA2 (round-14, at FMA floor) ==
#define HST 68
#define AWT2 132
#define K2_SMEM ((SEQ*HST + SEQ*AWT2 + SEQ + SEQ + HID + HID + SEQ) * 4 + SEQ * 4 * 4)

__global__ __launch_bounds__(128) void k2_gat1(const float* __restrict__ a_src,
                                               const float* __restrict__ a_dst,
                                               const float* __restrict__ b1) {
    extern __shared__ float sm[];
    float*    hs   = sm;
    float*    aw   = hs + SEQ * HST;
    float*    esrc = aw + SEQ * AWT2;
    float*    edst = esrc + SEQ;
    float*    avs  = edst + SEQ;
    float*    avd  = avs + HID;
    float*    rdsm = avd + HID;
    unsigned* mw   = (unsigned*)(rdsm + SEQ);

    int b = blockIdx.x, h = blockIdx.y;
    int tid = threadIdx.x, wid = tid >> 5, ln = tid & 31;

    const float* hb = g_h1 + ((size_t)b * SEQ) * D1 + h * HID;
    for (int i = tid; i < 2048; i += 128) {
        int s = i >> 4, q = i & 15;
        *(float4*)&hs[s * HST + 4 * q] = *(const float4*)(hb + (size_t)s * D1 + 4 * q);
    }
    if (tid < HID) { avs[tid] = a_src[h * HID + tid]; avd[tid] = a_dst[h * HID + tid]; }
    for (int i = tid; i < SEQ * 4; i += 128) mw[i] = g_mask[(size_t)b * SEQ * 4 + i];
    __syncthreads();

    {
        const float* hr = hs + tid * HST;
        float ps = 0.f, pd = 0.f;
#pragma unroll
        for (int c4 = 0; c4 < 16; c4++) {
            float4 hv = *(const float4*)&hr[4 * c4];
            float4 as = *(const float4*)&avs[4 * c4];
            float4 ad = *(const float4*)&avd[4 * c4];
            ps += hv.x * as.x + hv.y * as.y + hv.z * as.z + hv.w * as.w;
            pd += hv.x * ad.x + hv.y * ad.y + hv.z * ad.z + hv.w * ad.w;
        }
        esrc[tid] = ps; edst[tid] = pd;
    }
    __syncthreads();

    int tp = ln >> 3, cl = ln & 7;
    int cb = cl * 4;
    int s0 = ln * 4, sh = cl * 4;
    float4 es4 = *(const float4*)&esrc[s0];
    float* awme = aw + wid * 32 * AWT2;
    float4 ba = *(const float4*)(b1 + h * HID + cb);
    float4 bbq = *(const float4*)(b1 + h * HID + cb + 32);

    for (int tl = 0; tl < 32; tl++) {
        int t = wid * 32 + tl;
        float ed = edst[t];
        unsigned mword = mw[t * 4 + tp];
        float l0 = es4.x + ed; l0 = l0 > 0.f ? l0 : NEG_SLOPE * l0;
        float l1 = es4.y + ed; l1 = l1 > 0.f ? l1 : NEG_SLOPE * l1;
        float l2 = es4.z + ed; l2 = l2 > 0.f ? l2 : NEG_SLOPE * l2;
        float l3 = es4.w + ed; l3 = l3 > 0.f ? l3 : NEG_SLOPE * l3;
        if (!((mword >> (sh + 0)) & 1u)) l0 = NEG_INF;
        if (!((mword >> (sh + 1)) & 1u)) l1 = NEG_INF;
        if (!((mword >> (sh + 2)) & 1u)) l2 = NEG_INF;
        if (!((mword >> (sh + 3)) & 1u)) l3 = NEG_INF;
        *(float4*)&awme[tl * AWT2 + s0] =
            make_float4(__expf(l0), __expf(l1), __expf(l2), __expf(l3));
    }
    __syncwarp();

    {
        const float* row = &awme[ln * AWT2];
        ull s2 = 0ull, one = splat2(1.0f);
#pragma unroll 8
        for (int qq = 0; qq < 32; qq++) {
            ulonglong2 v = *(const ulonglong2*)&row[4 * qq];
            ffma2(s2, v.x, one); ffma2(s2, v.y, one);
        }
        float2 f = unpack2(s2);
        rdsm[wid * 32 + ln] = 1.0f / (f.x + f.y);
    }
    __syncwarp();

    ull acc2[8][4];
#pragma unroll
    for (int i = 0; i < 8; i++) { acc2[i][0]=0; acc2[i][1]=0; acc2[i][2]=0; acc2[i][3]=0; }

#pragma unroll 4
    for (int s = 0; s < SEQ; s++) {
        const float* hrow = hs + s * HST;
        ulonglong2 hA = *(const ulonglong2*)&hrow[cb];
        ulonglong2 hB = *(const ulonglong2*)&hrow[cb + 32];
#pragma unroll
        for (int i = 0; i < 8; i++) {
            float wv = awme[(tp + 4 * i) * AWT2 + s];
            ull ws = splat2(wv);
            ffma2(acc2[i][0], ws, hA.x); ffma2(acc2[i][1], ws, hA.y);
            ffma2(acc2[i][2], ws, hB.x); ffma2(acc2[i][3], ws, hB.y);
        }
    }

#pragma unroll
    for (int i = 0; i < 8; i++) {
        int t = wid * 32 + tp + 4 * i;
        float rd = rdsm[t];
        float* dst = g_out1 + ((size_t)b * SEQ + t) * D1 + h * HID;
        float2 a = unpack2(acc2[i][0]), bq = unpack2(acc2[i][1]);
        float2 c = unpack2(acc2[i][2]), d = unpack2(acc2[i][3]);
        *(float4*)(dst + cb) = make_float4(
            fmaxf(a.x * rd + ba.x, 0.f), fmaxf(a.y * rd + ba.y, 0.f),
            fmaxf(bq.x * rd + ba.z, 0.f), fmaxf(bq.y * rd + ba.w, 0.f));
        *(float4*)(dst + cb + 32) = make_float4(
            fmaxf(c.x * rd + bbq.x, 0.f), fmaxf(c.y * rd + bbq.y, 0.f),
            fmaxf(d.x * rd + bbq.z, 0.f), fmaxf(d.y * rd + bbq.w, 0.f));
    }
}

// ============ K3: h2 = out1 @ W2, 4r x 8c lanes, cp.async.bulk + mbarrier DB ============
// K3R=128 rows/block, 256 thr, 3 blocks/SM (grid 512 -> 1.15 waves).
// Staging via cp.async.bulk row copies (1 instr / 128B x-row, / 256B W2-row) issued by
// tid 0, transaction-counted on per-buffer mbarrier -> kills the per-16B cp.async
// issue tax (10.5M ops -> 1.3M). Buffer bf serves chunks c (c&1==bf); parity (c>>1)&1.
#define KC 32
#define XST 36
#define K3R 128
#define K3_XSF (K3R * XST)
#define K3_WSF (KC * 64)
#define K3_MBAR_OFF ((2 * K3_XSF + 2 * K3_WSF) * 4)
#define K3_SMEM (K3_MBAR_OFF + 16)
#define K3_BYTES (K3R * 128 + KC * 256)

__global__ __launch_bounds__(256, 3) void k3_gemm2(const float* __restrict__ W2) {
    extern __shared__ float k3sm[];
    int tid = threadIdx.x, wid = tid >> 5, ln = tid & 31;
    int row0 = blockIdx.x * K3R;
    int rb = wid * 16 + (ln >> 3) * 4;     // 4 consecutive rows
    int cb = (ln & 7) * 4;

    unsigned smbase;
    { unsigned long long gp = __cvta_generic_to_shared(k3sm); smbase = (unsigned)gp; }
    unsigned mbar0 = smbase + K3_MBAR_OFF, mbar1 = mbar0 + 8;

    if (tid == 0) { mbar_init(mbar0, 1); mbar_init(mbar1, 1); }
    __syncthreads();

    auto stage = [&](int bf, int k0) {
        if (tid == 0) {
            unsigned mb = bf ? mbar1 : mbar0;
            mbar_expect(mb, K3_BYTES);
            unsigned xsb = smbase + (unsigned)(bf * K3_XSF) * 4u;
            unsigned wsb = smbase + (unsigned)(2 * K3_XSF + bf * K3_WSF) * 4u;
            const float* xsrc = g_out1 + (size_t)row0 * D1 + k0;
#pragma unroll 4
            for (int r = 0; r < K3R; r++)
                bulkcp(xsb + (unsigned)(r * XST) * 4u, xsrc + (size_t)r * D1, 128, mb);
            const float* wsrc = W2 + (size_t)k0 * HID;
#pragma unroll 4
            for (int kk = 0; kk < KC; kk++)
                bulkcp(wsb + (unsigned)(kk * 64) * 4u, wsrc + (size_t)kk * HID, 256, mb);
        }
    };

    ull acc2[4][4];
#pragma unroll
    for (int p = 0; p < 4; p++) { acc2[p][0]=0; acc2[p][1]=0; acc2[p][2]=0; acc2[p][3]=0; }

    stage(0, 0);

    for (int c = 0; c < D1 / KC; c++) {
        if (c < D1 / KC - 1) stage((c + 1) & 1, (c + 1) * KC);
        mbar_wait((c & 1) ? mbar1 : mbar0, (c >> 1) & 1);
        __syncthreads();

        const float* xs = k3sm + (c & 1) * K3_XSF;
        const float* ws = k3sm + 2 * K3_XSF + (c & 1) * K3_WSF;
#pragma unroll
        for (int k = 0; k < KC; k++) {
            ulonglong2 wA = *(const ulonglong2*)&ws[k * 64 + cb];
            ulonglong2 wB = *(const ulonglong2*)&ws[k * 64 + cb + 32];
            float x0 = xs[(rb + 0) * XST + k];
            float x1 = xs[(rb + 1) * XST + k];
            float x2 = xs[(rb + 2) * XST + k];
            float x3 = xs[(rb + 3) * XST + k];
            ull s0 = splat2(x0), s1 = splat2(x1), s2 = splat2(x2), s3 = splat2(x3);
            ffma2(acc2[0][0], s0, wA.x); ffma2(acc2[0][1], s0, wA.y);
            ffma2(acc2[0][2], s0, wB.x); ffma2(acc2[0][3], s0, wB.y);
            ffma2(acc2[1][0], s1, wA.x); ffma2(acc2[1][1], s1, wA.y);
            ffma2(acc2[1][2], s1, wB.x); ffma2(acc2[1][3], s1, wB.y);
            ffma2(acc2[2][0], s2, wA.x); ffma2(acc2[2][1], s2, wA.y);
            ffma2(acc2[2][2], s2, wB.x); ffma2(acc2[2][3], s2, wB.y);
            ffma2(acc2[3][0], s3, wA.x); ffma2(acc2[3][1], s3, wA.y);
            ffma2(acc2[3][2], s3, wB.x); ffma2(acc2[3][3], s3, wB.y);
        }
        __syncthreads();
    }
#pragma unroll
    for (int p = 0; p < 4; p++) {
        int r = row0 + rb + p;
        float2 a = unpack2(acc2[p][0]), bq = unpack2(acc2[p][1]);
        float2 c2 = unpack2(acc2[p][2]), d = unpack2(acc2[p][3]);
        *(float4*)(g_h2 + (size_t)r * HID + cb)      = make_float4(a.x, a.y, bq.x, bq.y);
        *(float4*)(g_h2 + (size_t)r * HID + cb + 32) = make_float4(c2.x, c2.y, d.x, d.y);
    }
}

// ============ K4: layer-2 attention at t=S-1 only + final head ============
__global__ __launch_bounds__(128) void k4_final(const float* __restrict__ a_src2,
                                                const float* __restrict__ a_dst2,
                                                const float* __restrict__ b2,
                                                const float* __restrict__ Wf,
                                                const float* __restrict__ bf,
                                                float* __restrict__ out) {
    __shared__ float hsm[SEQ * HID];
    __shared__ float e2[SEQ];
    __shared__ float wsm[SEQ];
    __shared__ float sred[2];
    __shared__ float sinv, sed;
    int b = blockIdx.x;
    int tid = threadIdx.x, wid = tid >> 5, ln = tid & 31;

    for (int i = tid; i < SEQ * HID / 4; i += 128)
        *(float4*)&hsm[i * 4] = *(const float4*)(g_h2 + (size_t)b * SEQ * HID + i * 4);
    __syncthreads();

    for (int i = 0; i < 32; i++) {
        int s = wid * 32 + i;
        float ps = hsm[s * HID + ln] * a_src2[ln] + hsm[s * HID + ln + 32] * a_src2[ln + 32];
#pragma unroll
        for (int o = 16; o; o >>= 1) ps += __shfl_down_sync(~0u, ps, o);
        if (ln == 0) e2[s] = ps;
    }
    if (wid == 0) {
        float pd = hsm[127 * HID + ln] * a_dst2[ln] + hsm[127 * HID + ln + 32] * a_dst2[ln + 32];
#pragma unroll
        for (int o = 16; o; o >>= 1) pd += __shfl_down_sync(~0u, pd, o);
        if (ln == 0) sed = pd;
    }
    __syncthreads();

    if (wid == 0) {
        float ed = sed;
        int s0 = ln * 4;
        unsigned mword = g_mask[((size_t)b * SEQ + 127) * 4 + (ln >> 3)];
        int sh = (ln & 7) * 4;
        float l0 = e2[s0 + 0] + ed; l0 = l0 > 0.f ? l0 : NEG_SLOPE * l0;
        float l1 = e2[s0 + 1] + ed; l1 = l1 > 0.f ? l1 : NEG_SLOPE * l1;
        float l2 = e2[s0 + 2] + ed; l2 = l2 > 0.f ? l2 : NEG_SLOPE * l2;
        float l3 = e2[s0 + 3] + ed; l3 = l3 > 0.f ? l3 : NEG_SLOPE * l3;
        if (!((mword >> (sh + 0)) & 1u)) l0 = NEG_INF;
        if (!((mword >> (sh + 1)) & 1u)) l1 = NEG_INF;
        if (!((mword >> (sh + 2)) & 1u)) l2 = NEG_INF;
        if (!((mword >> (sh + 3)) & 1u)) l3 = NEG_INF;
        float w0 = __expf(l0), w1 = __expf(l1);
        float w2 = __expf(l2), w3 = __expf(l3);
        float su = (w0 + w1) + (w2 + w3);
#pragma unroll
        for (int o = 16; o; o >>= 1) su += __shfl_xor_sync(~0u, su, o);
        *(float4*)&wsm[s0] = make_float4(w0, w1, w2, w3);
        if (ln == 0) sinv = 1.0f / su;
    }
    __syncthreads();

    float val = 0.f;
    if (tid < HID) {
        float acc = 0.f;
        for (int s = 0; s < SEQ; s++) acc = fmaf(wsm[s], hsm[s * HID + tid], acc);
        val = fmaxf(acc * sinv + b2[tid], 0.f) * Wf[tid];
    }
#pragma unroll
    for (int o = 16; o; o >>= 1) val += __shfl_down_sync(~0u, val, o);
    if (ln == 0 && wid < 2) sred[wid] = val;
    __syncthreads();
    if (tid == 0) out[b] = 1.0f / (1.0f + __expf(-(sred[0] + sred[1] + bf[0])));
}

// ============ launch ============
extern "C" void kernel_launch(void* const* d_in, const int* in_sizes, int n_in,
                              void* d_out, int out_size) {
    const float* x      = (const float*)d_in[0];
    const int*   adj    = (const int*)d_in[1];
    const float* W1     = (const float*)d_in[2];
    const float* a_src1 = (const float*)d_in[3];
    const float* a_dst1 = (const float*)d_in[4];
    const float* b1     = (const float*)d_in[5];
    const float* W2     = (const float*)d_in[6];
    const float* a_src2 = (const float*)d_in[7];
    const float* a_dst2 = (const float*)d_in[8];
    const float* b2     = (const float*)d_in[9];
    const float* Wf     = (const float*)d_in[10];
    const float* bf     = (const float*)d_in[11];
    float* out = (float*)d_out;

    cudaFuncSetAttribute(k2_gat1, cudaFuncAttributeMaxDynamicSharedMemorySize, K2_SMEM);
    cudaFuncSetAttribute(k3_gemm2, cudaFuncAttributeMaxDynamicSharedMemorySize, K3_SMEM);

    k0_maskpack<<<B, SEQ>>>(adj);
    k1_gemm1<<<(B * SEQ) / 16, 256>>>(x, W1);
    k2_gat1<<<dim3(B, NH), 128, K2_SMEM>>>(a_src1, a_dst1, b1);
    k3_gemm2<<<(B * SEQ) / K3R, 256, K3_SMEM>>>(W2);
    k4_final<<<B, 128>>>(a_src2, a_dst2, b2, Wf, bf, out);
}